// round 14
// baseline (speedup 1.0000x reference)
#include <cuda_runtime.h>
#include <cuda_fp16.h>
#include <cstdint>

// Sparse embedding-bag: out[b,:] = bias + sum_k weight[ft_ics[b,k],:] * ft_vals[b,k]
// B=16384, K=32, N_OUT=256. Table 41024x256 fp32 = 42 MB.
//
// R14: FUSED persistent kernel. Phase 1: grid-stride fp32->fp16 table convert
// (streaming floor ~4.5us). Software grid barrier (monotonic atomic ticket --
// adds exactly gridDim.x per replay, no reset, graph-replay deterministic).
// Phase 2: LTS-cap gather (warp=row, 4 coalesced LDG.32/feature, KU=4),
// row-group loop. Eliminates the ~1.5-2us inter-kernel seam of the two-launch
// version. grid=740=148x5 with __launch_bounds__(256,5): co-residency (and
// barrier safety) guaranteed for any regs<=51 (measured body: 40).

#define N_IN_ROWS 41024
#define N_OUT_COLS 256
#define K_FEATS 32
#define ROWS_PER_BLOCK 8
#define KU 4
#define GRID_BLOCKS (148 * 5)
#define ROW_GROUPS  2048            // 16384 / ROWS_PER_BLOCK

__device__ __half    g_w16[(size_t)N_IN_ROWS * N_OUT_COLS];
__device__ unsigned  g_arrive = 0;  // monotonic barrier ticket (never reset)

__global__ __launch_bounds__(256, 5)
void ft_fused_kernel(const int* __restrict__ ics,
                     const float* __restrict__ vals,
                     const float4* __restrict__ w32,   // [N_IN*64] float4
                     const float* __restrict__ bias,   // [256]
                     float* __restrict__ out)          // [B][256]
{
    const int ty  = threadIdx.y;
    const int tx  = threadIdx.x;
    const int tid = ty * 32 + tx;

    // ---------------- phase 1: fp32 -> fp16 table (grid-stride) -------------
    {
        const size_t n4 = (size_t)N_IN_ROWS * N_OUT_COLS / 4;
        uint2* dst = reinterpret_cast<uint2*>(g_w16);
        for (size_t i = (size_t)blockIdx.x * 256 + tid;
             i < n4; i += (size_t)GRID_BLOCKS * 256) {
            const float4 w = __ldg(&w32[i]);
            __half2 h0 = __floats2half2_rn(w.x, w.y);
            __half2 h1 = __floats2half2_rn(w.z, w.w);
            uint2 u;
            u.x = *reinterpret_cast<unsigned*>(&h0);
            u.y = *reinterpret_cast<unsigned*>(&h1);
            dst[i] = u;   // write-back: table stays L2-resident
        }
    }

    // ---------------- grid barrier (monotonic ticket, no reset) -------------
    __threadfence();                      // phase-1 stores visible to all SMs
    __syncthreads();
    if (tid == 0) {
        const unsigned my = atomicAdd(&g_arrive, 1u) + 1u;
        // round up to next multiple of gridDim.x: each execution adds exactly
        // gridDim.x arrivals, so target is this execution's completion count.
        const unsigned target =
            ((my + (unsigned)gridDim.x - 1u) / (unsigned)gridDim.x) * (unsigned)gridDim.x;
        for (;;) {
            unsigned cur;
            asm volatile("ld.volatile.global.u32 %0, [%1];"
                         : "=r"(cur) : "l"(&g_arrive));
            if ((int)(cur - target) >= 0) break;
            __nanosleep(128);
        }
    }
    __syncthreads();
    __threadfence();                      // acquire: see all phase-1 writes

    // ---------------- phase 2: gather (row-group loop) ----------------------
    const __half2* wtab = reinterpret_cast<const __half2*>(g_w16);

    __shared__ int   s_idx[ROWS_PER_BLOCK][K_FEATS];
    __shared__ float s_val[ROWS_PER_BLOCK][K_FEATS];

    for (int rg = blockIdx.x; rg < ROW_GROUPS; rg += GRID_BLOCKS) {
        const int b = rg * ROWS_PER_BLOCK + ty;

        {
            const int   raw = __ldg(&ics[b * K_FEATS + tx]);
            const float v   = __ldg(&vals[b * K_FEATS + tx]);
            const bool valid = (raw >= 0);
            s_idx[ty][tx] = valid ? raw : 0;
            s_val[ty][tx] = valid ? v : 0.0f;
        }
        __syncwarp();

        float acc[8];
        #pragma unroll
        for (int c = 0; c < 4; ++c) {
            acc[2 * c]     = __ldg(&bias[c * 64 + 2 * tx]);
            acc[2 * c + 1] = __ldg(&bias[c * 64 + 2 * tx + 1]);
        }

        #pragma unroll
        for (int k0 = 0; k0 < K_FEATS; k0 += KU) {
            int   idx[KU];
            float v[KU];
            #pragma unroll
            for (int j = 0; j < KU; ++j) {
                idx[j] = s_idx[ty][k0 + j];
                v[j]   = s_val[ty][k0 + j];
            }

            // Front-batch 16 independent coalesced LDG.32 (one 128B line each).
            __half2 w[KU][4];
            #pragma unroll
            for (int j = 0; j < KU; ++j) {
                const __half2* base = wtab + (size_t)idx[j] * 128 + tx;
                #pragma unroll
                for (int c = 0; c < 4; ++c)
                    w[j][c] = __ldg(base + c * 32);
            }

            #pragma unroll
            for (int j = 0; j < KU; ++j) {
                #pragma unroll
                for (int c = 0; c < 4; ++c) {
                    const float2 wf = __half22float2(w[j][c]);
                    acc[2 * c]     = fmaf(v[j], wf.x, acc[2 * c]);
                    acc[2 * c + 1] = fmaf(v[j], wf.y, acc[2 * c + 1]);
                }
            }
        }

        float* orow = out + (size_t)b * N_OUT_COLS;
        #pragma unroll
        for (int c = 0; c < 4; ++c) {
            float2 o = make_float2(acc[2 * c], acc[2 * c + 1]);
            __stcs(reinterpret_cast<float2*>(orow + c * 64) + tx, o);
        }
        __syncwarp();   // protect s_idx/s_val reuse across row-groups
    }
}

extern "C" void kernel_launch(void* const* d_in, const int* in_sizes, int n_in,
                              void* d_out, int out_size)
{
    const int*    ics    = (const int*)d_in[0];
    const float*  vals   = (const float*)d_in[1];
    const float4* weight = (const float4*)d_in[2];
    const float*  bias   = (const float*)d_in[3];
    float*        out    = (float*)d_out;

    dim3 block(32, ROWS_PER_BLOCK);
    ft_fused_kernel<<<GRID_BLOCKS, block>>>(ics, vals, weight, bias, out);
}

// round 15
// speedup vs baseline: 1.2000x; 1.2000x over previous
#include <cuda_runtime.h>
#include <cuda_fp16.h>
#include <cstdint>

// Sparse embedding-bag: out[b,:] = bias + sum_k weight[ft_ics[b,k],:] * ft_vals[b,k]
// B=16384, K=32, N_OUT=256. Table 41024x256 fp32 = 42 MB.
//
// FINAL (converged, 15 rounds): fp16-table pre-pass + LTS-cap gather.
//  - Gather at the L2 random-line delivery floor (22.6 +/- 0.4us over 7 runs,
//    6 structural variants tied): warp=row, 4 coalesced LDG.32 per feature
//    (one fully-consumed 128B line each), KU=4 front-batched (16 loads in
//    flight), occ 6 blocks/SM, streaming float2 stores.
//  - Convert at the streaming floor (~4.5us): grid-stride float4, 2048 blocks,
//    write-back stores keep the 21MB fp16 table L2-resident across replays.
//  - Measured and rejected: LDG.128/.256 shapes (within-LDG replay floor),
//    FFMA2 packing, warp-split K, evict_first/last hints, flat one-shot
//    convert grids, fused persistent kernel with grid barrier (all neutral
//    or worse). Sub-fp16 blocked by the 1e-3 precision budget.

#define N_IN_ROWS 41024
#define N_OUT_COLS 256
#define K_FEATS 32
#define ROWS_PER_BLOCK 8
#define KU 4

__device__ __half g_w16[(size_t)N_IN_ROWS * N_OUT_COLS];

// ---------------- conversion: fp32 table -> fp16 table (streaming) ----------
__global__ __launch_bounds__(256)
void convert_w16_kernel(const float4* __restrict__ w32)
{
    const size_t n4 = (size_t)N_IN_ROWS * N_OUT_COLS / 4;
    uint2* dst = reinterpret_cast<uint2*>(g_w16);
    for (size_t i = (size_t)blockIdx.x * blockDim.x + threadIdx.x;
         i < n4; i += (size_t)gridDim.x * blockDim.x) {
        const float4 w = __ldg(&w32[i]);
        __half2 h0 = __floats2half2_rn(w.x, w.y);
        __half2 h1 = __floats2half2_rn(w.z, w.w);
        uint2 u;
        u.x = *reinterpret_cast<unsigned*>(&h0);
        u.y = *reinterpret_cast<unsigned*>(&h1);
        dst[i] = u;   // write-back: fp16 table stays L2-resident for the gather
    }
}

// ---------------- gather: fp16 table, fp32 accumulate -----------------------
// Warp = one batch row. Lane tx owns column pairs {c*64+2tx, +1 : c=0..3}.
// Each feature row = 128 half2; warp covers it with 4 coalesced LDG.32
// (one 128B line each). KU=4 features front-batched -> 16 loads in flight.
__global__ __launch_bounds__(32 * ROWS_PER_BLOCK, 6)
void ft_embed_bag_kernel(const int* __restrict__ ics,
                         const float* __restrict__ vals,
                         const float* __restrict__ bias,   // [256]
                         float* __restrict__ out)          // [B][256]
{
    __shared__ int   s_idx[ROWS_PER_BLOCK][K_FEATS];
    __shared__ float s_val[ROWS_PER_BLOCK][K_FEATS];

    const int ty = threadIdx.y;
    const int tx = threadIdx.x;
    const int b  = blockIdx.x * ROWS_PER_BLOCK + ty;

    {
        const int   raw = __ldg(&ics[b * K_FEATS + tx]);
        const float v   = __ldg(&vals[b * K_FEATS + tx]);
        const bool valid = (raw >= 0);
        s_idx[ty][tx] = valid ? raw : 0;
        s_val[ty][tx] = valid ? v : 0.0f;
    }
    __syncwarp();

    // acc[2c], acc[2c+1] = output cols c*64 + 2tx, c*64 + 2tx + 1
    float acc[8];
    #pragma unroll
    for (int c = 0; c < 4; ++c) {
        acc[2 * c]     = __ldg(&bias[c * 64 + 2 * tx]);
        acc[2 * c + 1] = __ldg(&bias[c * 64 + 2 * tx + 1]);
    }

    const __half2* wtab = reinterpret_cast<const __half2*>(g_w16);

    #pragma unroll
    for (int k0 = 0; k0 < K_FEATS; k0 += KU) {
        int   idx[KU];
        float v[KU];
        #pragma unroll
        for (int j = 0; j < KU; ++j) {
            idx[j] = s_idx[ty][k0 + j];
            v[j]   = s_val[ty][k0 + j];
        }

        // Front-batch 16 independent coalesced LDG.32 (one 128B line each).
        __half2 w[KU][4];
        #pragma unroll
        for (int j = 0; j < KU; ++j) {
            const __half2* base = wtab + (size_t)idx[j] * 128 + tx;
            #pragma unroll
            for (int c = 0; c < 4; ++c)
                w[j][c] = __ldg(base + c * 32);
        }

        #pragma unroll
        for (int j = 0; j < KU; ++j) {
            #pragma unroll
            for (int c = 0; c < 4; ++c) {
                const float2 wf = __half22float2(w[j][c]);
                acc[2 * c]     = fmaf(v[j], wf.x, acc[2 * c]);
                acc[2 * c + 1] = fmaf(v[j], wf.y, acc[2 * c + 1]);
            }
        }
    }

    // Streaming float2 stores (single-use output).
    float* orow = out + (size_t)b * N_OUT_COLS;
    #pragma unroll
    for (int c = 0; c < 4; ++c) {
        float2 o = make_float2(acc[2 * c], acc[2 * c + 1]);
        __stcs(reinterpret_cast<float2*>(orow + c * 64) + tx, o);
    }
}

extern "C" void kernel_launch(void* const* d_in, const int* in_sizes, int n_in,
                              void* d_out, int out_size)
{
    const int*    ics    = (const int*)d_in[0];
    const float*  vals   = (const float*)d_in[1];
    const float4* weight = (const float4*)d_in[2];
    const float*  bias   = (const float*)d_in[3];
    float*        out    = (float*)d_out;

    const int B = in_sizes[0] / K_FEATS;  // 16384

    convert_w16_kernel<<<2048, 256>>>(weight);

    dim3 block(32, ROWS_PER_BLOCK);
    dim3 grid(B / ROWS_PER_BLOCK);
    ft_embed_bag_kernel<<<grid, block>>>(ics, vals, bias, out);
}

// round 16
// speedup vs baseline: 1.2172x; 1.0143x over previous
#include <cuda_runtime.h>
#include <cuda_fp16.h>
#include <cstdint>

// Sparse embedding-bag: out[b,:] = bias + sum_k weight[ft_ics[b,k],:] * ft_vals[b,k]
// B=16384, K=32, N_OUT=256. Table 41024x256 fp32 = 42 MB.
//
// R16 = converged two-kernel config + PDL (programmatic dependent launch):
//  - convert (primary): fp32->fp16 table, grid-stride, streaming floor ~4.5us;
//    triggers programmatic launch completion right after its loop.
//  - gather (secondary, PDL): launched with programmaticStreamSerialization;
//    preamble (ics/vals loads, smem staging, bias) runs OVERLAPPED with the
//    convert's tail, then cudaGridDependencySynchronize() gates the first
//    g_w16 read. Hides the ~1-2.5us inter-kernel seam that fusion (R14)
//    failed to beat. Gather body = best-measured (KU=4, 4x LDG.32/feature,
//    occ 6 blocks/SM, 22.6 +/- 0.4us over 7 runs = LTS random-line floor).

#define N_IN_ROWS 41024
#define N_OUT_COLS 256
#define K_FEATS 32
#define ROWS_PER_BLOCK 8
#define KU 4

__device__ __half g_w16[(size_t)N_IN_ROWS * N_OUT_COLS];

// ---------------- conversion: fp32 table -> fp16 table (streaming) ----------
__global__ __launch_bounds__(256)
void convert_w16_kernel(const float4* __restrict__ w32)
{
    const size_t n4 = (size_t)N_IN_ROWS * N_OUT_COLS / 4;
    uint2* dst = reinterpret_cast<uint2*>(g_w16);
    for (size_t i = (size_t)blockIdx.x * blockDim.x + threadIdx.x;
         i < n4; i += (size_t)gridDim.x * blockDim.x) {
        const float4 w = __ldg(&w32[i]);
        __half2 h0 = __floats2half2_rn(w.x, w.y);
        __half2 h1 = __floats2half2_rn(w.z, w.w);
        uint2 u;
        u.x = *reinterpret_cast<unsigned*>(&h0);
        u.y = *reinterpret_cast<unsigned*>(&h1);
        dst[i] = u;   // write-back: fp16 table stays L2-resident for the gather
    }
    // Release the dependent (gather) grid as early as legal.
    cudaTriggerProgrammaticLaunchCompletion();
}

// ---------------- gather: fp16 table, fp32 accumulate (PDL secondary) -------
// Warp = one batch row. Lane tx owns column pairs {c*64+2tx, +1 : c=0..3}.
// Preamble (no g_w16 access) overlaps the convert; dependency sync gates
// the table reads.
__global__ __launch_bounds__(32 * ROWS_PER_BLOCK, 6)
void ft_embed_bag_kernel(const int* __restrict__ ics,
                         const float* __restrict__ vals,
                         const float* __restrict__ bias,   // [256]
                         float* __restrict__ out)          // [B][256]
{
    __shared__ int   s_idx[ROWS_PER_BLOCK][K_FEATS];
    __shared__ float s_val[ROWS_PER_BLOCK][K_FEATS];

    const int ty = threadIdx.y;
    const int tx = threadIdx.x;
    const int b  = blockIdx.x * ROWS_PER_BLOCK + ty;

    // ---- preamble: everything that does not touch g_w16 --------------------
    {
        const int   raw = __ldg(&ics[b * K_FEATS + tx]);
        const float v   = __ldg(&vals[b * K_FEATS + tx]);
        const bool valid = (raw >= 0);
        s_idx[ty][tx] = valid ? raw : 0;
        s_val[ty][tx] = valid ? v : 0.0f;
    }
    __syncwarp();

    // acc[2c], acc[2c+1] = output cols c*64 + 2tx, c*64 + 2tx + 1
    float acc[8];
    #pragma unroll
    for (int c = 0; c < 4; ++c) {
        acc[2 * c]     = __ldg(&bias[c * 64 + 2 * tx]);
        acc[2 * c + 1] = __ldg(&bias[c * 64 + 2 * tx + 1]);
    }

    // ---- gate: all convert stores visible before first table read ----------
    cudaGridDependencySynchronize();

    const __half2* wtab = reinterpret_cast<const __half2*>(g_w16);

    #pragma unroll
    for (int k0 = 0; k0 < K_FEATS; k0 += KU) {
        int   idx[KU];
        float v[KU];
        #pragma unroll
        for (int j = 0; j < KU; ++j) {
            idx[j] = s_idx[ty][k0 + j];
            v[j]   = s_val[ty][k0 + j];
        }

        // Front-batch 16 independent coalesced LDG.32 (one 128B line each).
        __half2 w[KU][4];
        #pragma unroll
        for (int j = 0; j < KU; ++j) {
            const __half2* base = wtab + (size_t)idx[j] * 128 + tx;
            #pragma unroll
            for (int c = 0; c < 4; ++c)
                w[j][c] = __ldg(base + c * 32);
        }

        #pragma unroll
        for (int j = 0; j < KU; ++j) {
            #pragma unroll
            for (int c = 0; c < 4; ++c) {
                const float2 wf = __half22float2(w[j][c]);
                acc[2 * c]     = fmaf(v[j], wf.x, acc[2 * c]);
                acc[2 * c + 1] = fmaf(v[j], wf.y, acc[2 * c + 1]);
            }
        }
    }

    // Streaming float2 stores (single-use output).
    float* orow = out + (size_t)b * N_OUT_COLS;
    #pragma unroll
    for (int c = 0; c < 4; ++c) {
        float2 o = make_float2(acc[2 * c], acc[2 * c + 1]);
        __stcs(reinterpret_cast<float2*>(orow + c * 64) + tx, o);
    }
}

extern "C" void kernel_launch(void* const* d_in, const int* in_sizes, int n_in,
                              void* d_out, int out_size)
{
    const int*    ics    = (const int*)d_in[0];
    const float*  vals   = (const float*)d_in[1];
    const float4* weight = (const float4*)d_in[2];
    const float*  bias   = (const float*)d_in[3];
    float*        out    = (float*)d_out;

    const int B = in_sizes[0] / K_FEATS;  // 16384

    convert_w16_kernel<<<2048, 256>>>(weight);

    // Secondary with programmatic dependent launch: preamble overlaps the
    // convert's tail; cudaGridDependencySynchronize() inside gates g_w16 reads.
    cudaLaunchConfig_t cfg = {};
    cfg.gridDim  = dim3(B / ROWS_PER_BLOCK);
    cfg.blockDim = dim3(32, ROWS_PER_BLOCK);
    cfg.stream   = 0;
    cudaLaunchAttribute attr[1];
    attr[0].id = cudaLaunchAttributeProgrammaticStreamSerialization;
    attr[0].val.programmaticStreamSerializationAllowed = 1;
    cfg.attrs    = attr;
    cfg.numAttrs = 1;
    cudaLaunchKernelEx(&cfg, ft_embed_bag_kernel, ics, vals, bias, out);
}

// round 17
// speedup vs baseline: 1.3034x; 1.0708x over previous
#include <cuda_runtime.h>
#include <cuda_fp16.h>
#include <cstdint>

// Sparse embedding-bag: out[b,:] = bias + sum_k weight[ft_ics[b,k],:] * ft_vals[b,k]
// B=16384, K=32, N_OUT=256. Table 41024x256 fp32 = 42 MB.
//
// R17 (terminal): the whole problem is at the LTS chip-throughput byte floor:
//   convert 63MB + gather 268MB + io 20MB = 351MB @ ~12TB/s = ~29.2us,
// matching the last five measurements. Gather = 100% of LTS line rate (each
// random 128B line fully consumed). Both seams are PDL-hidden:
//  - gather depends on convert via programmatic serialization; its preamble
//    (ics/vals/bias, no g_w16 access) overlaps the convert tail, gated by
//    cudaGridDependencySynchronize().
//  - convert ALSO carries the PDL attribute: the gather triggers programmatic
//    completion right after its gate, so NEXT replay's convert ramps under
//    this replay's gather tail. Benign race: convert rewrites g_w16 with
//    byte-identical values every replay (4B reads vs identical stores).

#define N_IN_ROWS 41024
#define N_OUT_COLS 256
#define K_FEATS 32
#define ROWS_PER_BLOCK 8
#define KU 4

__device__ __half g_w16[(size_t)N_IN_ROWS * N_OUT_COLS];

// ---------------- conversion: fp32 table -> fp16 table (streaming) ----------
__global__ __launch_bounds__(256)
void convert_w16_kernel(const float4* __restrict__ w32)
{
    const size_t n4 = (size_t)N_IN_ROWS * N_OUT_COLS / 4;
    uint2* dst = reinterpret_cast<uint2*>(g_w16);
    for (size_t i = (size_t)blockIdx.x * blockDim.x + threadIdx.x;
         i < n4; i += (size_t)gridDim.x * blockDim.x) {
        const float4 w = __ldg(&w32[i]);
        __half2 h0 = __floats2half2_rn(w.x, w.y);
        __half2 h1 = __floats2half2_rn(w.z, w.w);
        uint2 u;
        u.x = *reinterpret_cast<unsigned*>(&h0);
        u.y = *reinterpret_cast<unsigned*>(&h1);
        dst[i] = u;   // write-back: fp16 table stays L2-resident for the gather
    }
    // Release the dependent gather grid as early as legal.
    cudaTriggerProgrammaticLaunchCompletion();
}

// ---------------- gather: fp16 table, fp32 accumulate (PDL secondary) -------
// Warp = one batch row. Lane tx owns column pairs {c*64+2tx, +1 : c=0..3}.
// 4 coalesced LDG.32 per feature (one fully-consumed 128B line each), KU=4
// front-batched -> 16 loads in flight. Occ 6 blocks/SM.
__global__ __launch_bounds__(32 * ROWS_PER_BLOCK, 6)
void ft_embed_bag_kernel(const int* __restrict__ ics,
                         const float* __restrict__ vals,
                         const float* __restrict__ bias,   // [256]
                         float* __restrict__ out)          // [B][256]
{
    __shared__ int   s_idx[ROWS_PER_BLOCK][K_FEATS];
    __shared__ float s_val[ROWS_PER_BLOCK][K_FEATS];

    const int ty = threadIdx.y;
    const int tx = threadIdx.x;
    const int b  = blockIdx.x * ROWS_PER_BLOCK + ty;

    // ---- preamble: everything that does not touch g_w16 --------------------
    {
        const int   raw = __ldg(&ics[b * K_FEATS + tx]);
        const float v   = __ldg(&vals[b * K_FEATS + tx]);
        const bool valid = (raw >= 0);
        s_idx[ty][tx] = valid ? raw : 0;
        s_val[ty][tx] = valid ? v : 0.0f;
    }
    __syncwarp();

    float acc[8];
    #pragma unroll
    for (int c = 0; c < 4; ++c) {
        acc[2 * c]     = __ldg(&bias[c * 64 + 2 * tx]);
        acc[2 * c + 1] = __ldg(&bias[c * 64 + 2 * tx + 1]);
    }

    // ---- gate: all convert stores visible before first table read ----------
    cudaGridDependencySynchronize();
    // Release NEXT replay's convert to ramp under this gather's execution
    // (benign: it rewrites g_w16 with identical bytes).
    cudaTriggerProgrammaticLaunchCompletion();

    const __half2* wtab = reinterpret_cast<const __half2*>(g_w16);

    #pragma unroll
    for (int k0 = 0; k0 < K_FEATS; k0 += KU) {
        int   idx[KU];
        float v[KU];
        #pragma unroll
        for (int j = 0; j < KU; ++j) {
            idx[j] = s_idx[ty][k0 + j];
            v[j]   = s_val[ty][k0 + j];
        }

        // Front-batch 16 independent coalesced LDG.32 (one 128B line each).
        __half2 w[KU][4];
        #pragma unroll
        for (int j = 0; j < KU; ++j) {
            const __half2* base = wtab + (size_t)idx[j] * 128 + tx;
            #pragma unroll
            for (int c = 0; c < 4; ++c)
                w[j][c] = __ldg(base + c * 32);
        }

        #pragma unroll
        for (int j = 0; j < KU; ++j) {
            #pragma unroll
            for (int c = 0; c < 4; ++c) {
                const float2 wf = __half22float2(w[j][c]);
                acc[2 * c]     = fmaf(v[j], wf.x, acc[2 * c]);
                acc[2 * c + 1] = fmaf(v[j], wf.y, acc[2 * c + 1]);
            }
        }
    }

    // Streaming float2 stores (single-use output).
    float* orow = out + (size_t)b * N_OUT_COLS;
    #pragma unroll
    for (int c = 0; c < 4; ++c) {
        float2 o = make_float2(acc[2 * c], acc[2 * c + 1]);
        __stcs(reinterpret_cast<float2*>(orow + c * 64) + tx, o);
    }
}

extern "C" void kernel_launch(void* const* d_in, const int* in_sizes, int n_in,
                              void* d_out, int out_size)
{
    const int*    ics    = (const int*)d_in[0];
    const float*  vals   = (const float*)d_in[1];
    const float4* weight = (const float4*)d_in[2];
    const float*  bias   = (const float*)d_in[3];
    float*        out    = (float*)d_out;

    const int B = in_sizes[0] / K_FEATS;  // 16384

    cudaLaunchAttribute pdl[1];
    pdl[0].id = cudaLaunchAttributeProgrammaticStreamSerialization;
    pdl[0].val.programmaticStreamSerializationAllowed = 1;

    // Convert: PDL secondary w.r.t. previous replay's gather (overlaps its
    // tail across graph-replay boundaries; no data dependency on it).
    cudaLaunchConfig_t cv = {};
    cv.gridDim  = dim3(2048);
    cv.blockDim = dim3(256);
    cv.stream   = 0;
    cv.attrs    = pdl;
    cv.numAttrs = 1;
    cudaLaunchKernelEx(&cv, convert_w16_kernel, weight);

    // Gather: PDL secondary w.r.t. the convert; preamble overlaps its tail.
    cudaLaunchConfig_t gt = {};
    gt.gridDim  = dim3(B / ROWS_PER_BLOCK);
    gt.blockDim = dim3(32, ROWS_PER_BLOCK);
    gt.stream   = 0;
    gt.attrs    = pdl;
    gt.numAttrs = 1;
    cudaLaunchKernelEx(&gt, ft_embed_bag_kernel, ics, vals, bias, out);
}